// round 15
// baseline (speedup 1.0000x reference)
#include <cuda_runtime.h>

// Problem constants
#define Bq 4
#define Hq 256
#define Wq 256
#define Zq 64
#define ITER 8
#define EPS 1e-6

constexpr int N    = Bq * Hq * Wq * Zq;   // 16,777,216
constexpr int SAMP = Hq * Wq * Zq;        // 4,194,304
#define NT 256
constexpr int OCC  = 5;                   // co-residency bound (740 slots)
constexpr int SBLK = 128;                 // blocks per sample (divides TPS!)
constexpr int GRID = SBLK * Bq;           // 512 blocks, all co-resident
constexpr int TPS  = SAMP / (NT * 4);     // 4096 tiles; 32 per block exactly
constexpr int WZ   = Wq * Zq;

// Scratch (device globals; allocation forbidden). Write-once versioning:
// each r_k / w_k array is written exactly once, read only after -> no
// stale-L1 hazard across phases of the persistent kernel.
__device__ float g_r[ITER - 1][N];    // r_0..r_6 (r_7 never stored)
__device__ float g_w[ITER - 1][N];    // w_0..w_6 (w_7 never stored)

__device__ double   g_rho[ITER][Bq];  // direct r_k.r_k
__device__ double   g_tau[ITER][Bq];  // r_k.w_k
__device__ double   g_sig[ITER][Bq];  // r_k.w_{k-1}  (sig[0] unused)
__device__ double   g_om [ITER][Bq];  // w_k.w_k
__device__ double   g_loss;
__device__ unsigned g_max;

// per-sample barriers (count self-resets; gen monotonic across replays)
__device__ unsigned g_bar_count[Bq];
__device__ unsigned g_bar_gen[Bq];

// ---------------------------------------------------------------------------
// helpers
// ---------------------------------------------------------------------------

__device__ __forceinline__ float4 ld4(const float* __restrict__ p) {
    return *reinterpret_cast<const float4*>(p);
}
__device__ __forceinline__ float4 ld4cs(const float* __restrict__ p) {
    return __ldcs(reinterpret_cast<const float4*>(p));
}
__device__ __forceinline__ void st4(float* __restrict__ p, float4 v) {
    *reinterpret_cast<float4*>(p) = v;
}
__device__ __forceinline__ float dot4(float4 a, float4 b) {
    return a.x * b.x + a.y * b.y + a.z * b.z + a.w * b.w;
}

// 7-pt Laplacian; z-neighbors via lane shuffle (16 lanes tile one z-line;
// lane-boundary shuffles masked by z0). Call from ALL lanes.
__device__ __forceinline__ float4 lap(float4 c, float4 xm, float4 xp,
                                      float4 ym, float4 yp, int z0) {
    float zl = __shfl_up_sync(0xffffffffu, c.w, 1);
    float zr = __shfl_down_sync(0xffffffffu, c.x, 1);
    if (z0 == 0)  zl = 0.f;
    if (z0 == 60) zr = 0.f;
    float4 o;
    o.x = 6.f * c.x - xm.x - xp.x - ym.x - yp.x - zl  - c.y;
    o.y = 6.f * c.y - xm.y - xp.y - ym.y - yp.y - c.x - c.z;
    o.z = 6.f * c.z - xm.z - xp.z - ym.z - yp.z - c.y - c.w;
    o.w = 6.f * c.w - xm.w - xp.w - ym.w - yp.w - c.z - zr;
    return o;
}

// load 7-pt neighborhood of arr and return lap; center via *cen
__device__ __forceinline__ float4 lap_of(const float* __restrict__ arr,
                                         int i, int z0, bool w1, bool e1,
                                         bool n1, bool s1, float4* cen) {
    const float4 Zv = make_float4(0.f, 0.f, 0.f, 0.f);
    float4 c  = ld4(arr + i);
    float4 xm = w1 ? ld4(arr + i - Zq) : Zv;
    float4 xp = e1 ? ld4(arr + i + Zq) : Zv;
    float4 ym = n1 ? ld4(arr + i - WZ) : Zv;
    float4 yp = s1 ? ld4(arr + i + WZ) : Zv;
    *cen = c;
    return lap(c, xm, xp, ym, yp, z0);
}

__device__ __forceinline__ void block_reduce_add(float val, double* target) {
    __syncthreads();
    #pragma unroll
    for (int o = 16; o; o >>= 1)
        val += __shfl_xor_sync(0xffffffffu, val, o);
    __shared__ double sh[NT / 32];
    int lane = threadIdx.x & 31, wid = threadIdx.x >> 5;
    if (lane == 0) sh[wid] = (double)val;
    __syncthreads();
    if (threadIdx.x == 0) {
        double s = 0.0;
        #pragma unroll
        for (int k = 0; k < NT / 32; ++k) s += sh[k];
        atomicAdd(target, s);
    }
}

__device__ __forceinline__ void block_reduce4(float v0, float v1, float v2,
                                              float v3, double* t0, double* t1,
                                              double* t2, double* t3) {
    __syncthreads();
    #pragma unroll
    for (int o = 16; o; o >>= 1) {
        v0 += __shfl_xor_sync(0xffffffffu, v0, o);
        v1 += __shfl_xor_sync(0xffffffffu, v1, o);
        v2 += __shfl_xor_sync(0xffffffffu, v2, o);
        v3 += __shfl_xor_sync(0xffffffffu, v3, o);
    }
    __shared__ double sh[4][NT / 32];
    int lane = threadIdx.x & 31, wid = threadIdx.x >> 5;
    if (lane == 0) {
        sh[0][wid] = v0; sh[1][wid] = v1; sh[2][wid] = v2; sh[3][wid] = v3;
    }
    __syncthreads();
    if (threadIdx.x < 4) {
        double s = 0.0;
        #pragma unroll
        for (int k = 0; k < NT / 32; ++k) s += sh[threadIdx.x][k];
        double* tgt = (threadIdx.x == 0) ? t0 : (threadIdx.x == 1) ? t1
                    : (threadIdx.x == 2) ? t2 : t3;
        atomicAdd(tgt, s);
    }
}

__device__ __forceinline__ void block_reduce_max(float val, unsigned* target) {
    __syncthreads();
    #pragma unroll
    for (int o = 16; o; o >>= 1)
        val = fmaxf(val, __shfl_xor_sync(0xffffffffu, val, o));
    __shared__ float shm[NT / 32];
    int lane = threadIdx.x & 31, wid = threadIdx.x >> 5;
    if (lane == 0) shm[wid] = val;
    __syncthreads();
    if (threadIdx.x == 0) {
        float m = 0.f;
        #pragma unroll
        for (int k = 0; k < NT / 32; ++k) m = fmaxf(m, shm[k]);
        atomicMax(target, __float_as_uint(m));
    }
}

// per-sample grid barrier: only the SBLK blocks of sample sb participate.
__device__ __forceinline__ void sample_sync(int sb) {
    __syncthreads();
    if (threadIdx.x == 0) {
        unsigned my = *(volatile unsigned*)&g_bar_gen[sb];   // read BEFORE arrive
        __threadfence();
        if (atomicAdd(&g_bar_count[sb], 1) == SBLK - 1) {
            g_bar_count[sb] = 0;
            __threadfence();
            atomicAdd(&g_bar_gen[sb], 1);
        } else {
            while (*(volatile unsigned*)&g_bar_gen[sb] == my) __nanosleep(64);
        }
        __threadfence();
    }
    __syncthreads();
}

__device__ __forceinline__ void decode(int sb, int t, int& i, int& z0,
                                       int& wi, int& h) {
    i  = (sb << 22) + (t * NT + (int)threadIdx.x) * 4;
    z0 = i & 63;
    wi = (i >> 6) & 255;
    h  = (i >> 14) & 255;
}

// Scalar replay (double, fixed op order — deterministic on every block):
// alpha_{k-1} and beta_k from the stored dot arrays.
//   eta_0 = tau_0; alpha_j = rho_j/(eta_j+EPS)
//   beta_{j+1} = (rho_j - 2 a tau_j + a^2 om_j)/(rho_j+EPS)
//   eta_{j+1} = tau_{j+1} + b sig_{j+1} + b^2 eta_j
__device__ __forceinline__ void replay(int k, int sb, double& al, double& bt) {
    double eta = __ldcg(&g_tau[0][sb]);
    al = 0.0; bt = 0.0;
    for (int j = 1; j <= k; ++j) {
        double r = __ldcg(&g_rho[j - 1][sb]);
        double t = __ldcg(&g_tau[j - 1][sb]);
        double o = __ldcg(&g_om [j - 1][sb]);
        al = r / (eta + EPS);
        double rr = r - 2.0 * al * t + al * al * o;
        bt = rr / (r + EPS);
        if (j < k) {
            double tj = __ldcg(&g_tau[j][sb]);
            double sj = __ldcg(&g_sig[j][sb]);
            eta = tj + bt * sj + bt * bt * eta;
        }
    }
}

// ---------------------------------------------------------------------------
// kernels
// ---------------------------------------------------------------------------

__global__ void k_zero() {
    int t = threadIdx.x;
    if (t < ITER * Bq) {
        ((double*)g_rho)[t] = 0.0;
        ((double*)g_tau)[t] = 0.0;
        ((double*)g_sig)[t] = 0.0;
        ((double*)g_om)[t]  = 0.0;
    }
    if (t == 0) { g_loss = 0.0; g_max = 0u; }
}

__global__ void __launch_bounds__(NT, OCC)
k_cg(const float* __restrict__ x0, const float* __restrict__ bin,
     const float* __restrict__ ref, float* __restrict__ out) {
    const int sb   = (int)blockIdx.x & 3;
    const int sblk = (int)blockIdx.x >> 2;   // 0..SBLK-1
    __shared__ float s_a, s_b;

    // ---- P0 (asc): r0 = b - A x0 ; rho0 ----
    {
        float acc = 0.f;
        for (int t = sblk; t < TPS; t += SBLK) {
            int i, z0, wi, h; decode(sb, t, i, z0, wi, h);
            float4 xc;
            float4 ax = lap_of(x0, i, z0, wi > 0, wi < Wq - 1,
                               h > 0, h < Hq - 1, &xc);
            float4 bb = ld4cs(bin + i);
            float4 r0 = make_float4(bb.x - ax.x, bb.y - ax.y,
                                    bb.z - ax.z, bb.w - ax.w);
            st4(g_r[0] + i, r0);
            acc += dot4(r0, r0);
        }
        block_reduce_add(acc, &g_rho[0][sb]);
    }
    sample_sync(sb);

    // ---- P1 (desc): w0 = A r0 (store) ; tau0 = r0.w0 ; om0 = w0.w0 ----
    {
        float accT = 0.f, accO = 0.f;
        for (int t = sblk; t < TPS; t += SBLK) {
            int tt = TPS - 1 - t;
            int i, z0, wi, h; decode(sb, tt, i, z0, wi, h);
            float4 rc;
            float4 w = lap_of(g_r[0], i, z0, wi > 0, wi < Wq - 1,
                              h > 0, h < Hq - 1, &rc);
            st4(g_w[0] + i, w);
            accT += dot4(rc, w);
            accO += dot4(w, w);
        }
        block_reduce4(accT, accO, 0.f, 0.f,
                      &g_tau[0][sb], &g_om[0][sb],
                      &g_sig[0][sb], &g_sig[0][sb]);
    }
    sample_sync(sb);

    // ---- phases k = 1..7: two 7-pt stencils (r,w), one CG iter each.
    //      k=7: pure-read phase (neither r_7 nor w_7 stored) ----
    for (int k = 1; k < ITER; ++k) {
        if (threadIdx.x == 0) {
            double al, bt;
            replay(k, sb, al, bt);      // alpha_{k-1}, beta_k
            s_a = (float)al;
            s_b = (float)bt;
        }
        __syncthreads();
        const float al = s_a, bk = s_b;
        const float* rin = g_r[k - 1];
        const float* win = g_w[k - 1];
        const bool last = (k == ITER - 1);
        float* rout = last ? nullptr : g_r[k];
        float* wout = last ? nullptr : g_w[k];
        const bool rev = !(k & 1);
        float accR = 0.f, accT = 0.f, accS = 0.f, accO = 0.f;

        for (int t = sblk; t < TPS; t += SBLK) {
            int tt = rev ? TPS - 1 - t : t;
            int i, z0, wi, h; decode(sb, tt, i, z0, wi, h);
            bool w1 = wi > 0, e1 = wi < Wq - 1, n1 = h > 0, s1 = h < Hq - 1;

            float4 rc, wc;
            float4 lr = lap_of(rin, i, z0, w1, e1, n1, s1, &rc);  // A r_{k-1}
            float4 lw = lap_of(win, i, z0, w1, e1, n1, s1, &wc);  // A w_{k-1}

            // r_k = r_{k-1} - alpha w_{k-1}
            float4 rk = make_float4(rc.x - al * wc.x, rc.y - al * wc.y,
                                    rc.z - al * wc.z, rc.w - al * wc.w);
            if (!last) st4(rout + i, rk);
            // A r_k = A r_{k-1} - alpha A w_{k-1}
            float4 ark = make_float4(lr.x - al * lw.x, lr.y - al * lw.y,
                                     lr.z - al * lw.z, lr.w - al * lw.w);
            // w_k = A r_k + beta_k w_{k-1}
            float4 wk = make_float4(ark.x + bk * wc.x, ark.y + bk * wc.y,
                                    ark.z + bk * wc.z, ark.w + bk * wc.w);
            if (!last) st4(wout + i, wk);

            accR += dot4(rk, rk);
            accT += dot4(rk, wk);
            accS += dot4(rk, wc);
            accO += dot4(wk, wk);
        }
        block_reduce4(accR, accT, accS, accO,
                      &g_rho[k][sb], &g_tau[k][sb],
                      &g_sig[k][sb], &g_om[k][sb]);
        sample_sync(sb);
    }

    // ---- final (desc): x = x0 + sum_{j<=6} c'_j r_j + d*w6 ----
    // c_7 = alpha_7 ; c_j = alpha_j + beta_{j+1} c_{j+1}
    // r_7 = r_6 - alpha_6 w_6  =>  c'_6 = c_6 + c_7 ; d = -c_7*alpha_6
    {
        __shared__ float s_c[ITER];   // s_c[0..6] for r_0..r_6, s_c[7] for w6
        if (threadIdx.x == 0) {
            double alpha[ITER], beta[ITER];
            double eta = __ldcg(&g_tau[0][sb]);
            for (int j = 0; j < ITER; ++j) {
                double r = __ldcg(&g_rho[j][sb]);
                double a = r / (eta + EPS);
                alpha[j] = a;
                if (j < ITER - 1) {
                    double t = __ldcg(&g_tau[j][sb]);
                    double o = __ldcg(&g_om[j][sb]);
                    double rr = r - 2.0 * a * t + a * a * o;
                    double b = rr / (r + EPS);
                    beta[j + 1] = b;
                    double tj = __ldcg(&g_tau[j + 1][sb]);
                    double sj = __ldcg(&g_sig[j + 1][sb]);
                    eta = tj + b * sj + b * b * eta;
                }
            }
            double c[ITER];
            c[ITER - 1] = alpha[ITER - 1];
            for (int j = ITER - 2; j >= 0; --j)
                c[j] = alpha[j] + beta[j + 1] * c[j + 1];
            for (int j = 0; j < ITER - 2; ++j) s_c[j] = (float)c[j];
            s_c[ITER - 2] = (float)(c[ITER - 2] + c[ITER - 1]);       // r_6
            s_c[ITER - 1] = (float)(-c[ITER - 1] * alpha[ITER - 2]);  // w_6
        }
        __syncthreads();

        float accL = 0.f, mx = 0.f;
        for (int t = sblk; t < TPS; t += SBLK) {
            int tt = TPS - 1 - t;
            int i, z0, wi, h; decode(sb, tt, i, z0, wi, h);
            float4 x = ld4cs(x0 + i);
            #pragma unroll
            for (int k = 0; k < ITER - 1; ++k) {
                float c = s_c[k];
                float4 rk = ld4cs(g_r[k] + i);
                x.x += c * rk.x; x.y += c * rk.y;
                x.z += c * rk.z; x.w += c * rk.w;
            }
            {
                float d = s_c[ITER - 1];
                float4 w6 = ld4cs(g_w[ITER - 2] + i);
                x.x += d * w6.x; x.y += d * w6.y;
                x.z += d * w6.z; x.w += d * w6.w;
            }
            __stcs(out + 1 + i + 0, x.x);
            __stcs(out + 1 + i + 1, x.y);
            __stcs(out + 1 + i + 2, x.z);
            __stcs(out + 1 + i + 3, x.w);

            float4 rf = ld4cs(ref + i);
            float dx = x.x - rf.x, dy = x.y - rf.y;
            float dz = x.z - rf.z, dw = x.w - rf.w;
            accL += dx * dx + dy * dy + dz * dz + dw * dw;
            mx = fmaxf(mx, fmaxf(fmaxf(fabsf(dx), fabsf(dy)),
                                 fmaxf(fabsf(dz), fabsf(dw))));
        }
        block_reduce_add(accL, &g_loss);
        block_reduce_max(mx, &g_max);
    }
}

__global__ void k_writeout(float* __restrict__ out) {
    out[0] = (float)(g_loss / (double)N);
    out[N + 1] = __uint_as_float(g_max);
    // rho_8 per sample via the same scalar replay + one recurrence step
    double s = 0.0;
    for (int sb = 0; sb < Bq; ++sb) {
        double eta = g_tau[0][sb];
        double rho8 = 0.0;
        for (int j = 0; j < ITER; ++j) {
            double r = g_rho[j][sb];
            double a = r / (eta + EPS);
            double t = g_tau[j][sb];
            double o = g_om[j][sb];
            double rr = r - 2.0 * a * t + a * a * o;
            if (j == ITER - 1) { rho8 = rr; break; }
            double b = rr / (r + EPS);
            double tj = g_tau[j + 1][sb];
            double sj = g_sig[j + 1][sb];
            eta = tj + b * sj + b * b * eta;
        }
        s += rho8;
    }
    out[N + 2] = (float)(s / (double)Bq);
}

// ---------------------------------------------------------------------------

extern "C" void kernel_launch(void* const* d_in, const int* in_sizes, int n_in,
                              void* d_out, int out_size) {
    const float* x   = (const float*)d_in[0];
    const float* b   = (const float*)d_in[1];
    const float* ref = (const float*)d_in[2];
    float* out = (float*)d_out;

    k_zero<<<1, 64>>>();
    k_cg<<<GRID, NT>>>(x, b, ref, out);
    k_writeout<<<1, 1>>>(out);
}

// round 16
// speedup vs baseline: 1.0908x; 1.0908x over previous
#include <cuda_runtime.h>

// Problem constants
#define Bq 4
#define Hq 256
#define Wq 256
#define Zq 64
#define ITER 8
#define EPS 1e-6

constexpr int N    = Bq * Hq * Wq * Zq;   // 16,777,216
constexpr int SAMP = Hq * Wq * Zq;        // 4,194,304
#define NT 256
constexpr int OCC  = 5;
constexpr int GRID = 148 * OCC;           // 740 blocks, co-resident
constexpr int SBLK = GRID / Bq;           // 185 blocks per sample
constexpr int TPS  = SAMP / (NT * 4);     // 4096 tiles per sample
constexpr int WZ   = Wq * Zq;

// Scratch (device globals; allocation forbidden). Write-once versioning:
// each r_k / w_k array is written exactly once, read only after -> no
// stale-L1 hazard across phases of the persistent kernel.
__device__ float g_r[ITER - 1][N];    // r_0..r_6 (r_7 never stored)
__device__ float g_w[ITER - 1][N];    // w_0..w_6 (w_7 never stored)

__device__ double   g_rho[ITER][Bq];  // direct r_k.r_k
__device__ double   g_tau[ITER][Bq];  // r_k.w_k
__device__ double   g_sig[ITER][Bq];  // r_k.w_{k-1}  (sig[0] unused)
__device__ double   g_om [ITER][Bq];  // w_k.w_k
__device__ double   g_loss;
__device__ unsigned g_max;

// per-sample barriers (count self-resets; gen monotonic across replays)
__device__ unsigned g_bar_count[Bq];
__device__ unsigned g_bar_gen[Bq];

// ---------------------------------------------------------------------------
// helpers
// ---------------------------------------------------------------------------

__device__ __forceinline__ float4 ld4(const float* __restrict__ p) {
    return *reinterpret_cast<const float4*>(p);
}
__device__ __forceinline__ float4 ld4cs(const float* __restrict__ p) {
    return __ldcs(reinterpret_cast<const float4*>(p));
}
__device__ __forceinline__ void st4(float* __restrict__ p, float4 v) {
    *reinterpret_cast<float4*>(p) = v;
}
__device__ __forceinline__ float dot4(float4 a, float4 b) {
    return a.x * b.x + a.y * b.y + a.z * b.z + a.w * b.w;
}

// 7-pt Laplacian; z-neighbors via lane shuffle (16 lanes tile one z-line;
// lane-boundary shuffles masked by z0). Call from ALL lanes.
__device__ __forceinline__ float4 lap(float4 c, float4 xm, float4 xp,
                                      float4 ym, float4 yp, int z0) {
    float zl = __shfl_up_sync(0xffffffffu, c.w, 1);
    float zr = __shfl_down_sync(0xffffffffu, c.x, 1);
    if (z0 == 0)  zl = 0.f;
    if (z0 == 60) zr = 0.f;
    float4 o;
    o.x = 6.f * c.x - xm.x - xp.x - ym.x - yp.x - zl  - c.y;
    o.y = 6.f * c.y - xm.y - xp.y - ym.y - yp.y - c.x - c.z;
    o.z = 6.f * c.z - xm.z - xp.z - ym.z - yp.z - c.y - c.w;
    o.w = 6.f * c.w - xm.w - xp.w - ym.w - yp.w - c.z - zr;
    return o;
}

// load 7-pt neighborhood of arr and return lap; center via *cen
__device__ __forceinline__ float4 lap_of(const float* __restrict__ arr,
                                         int i, int z0, bool w1, bool e1,
                                         bool n1, bool s1, float4* cen) {
    const float4 Zv = make_float4(0.f, 0.f, 0.f, 0.f);
    float4 c  = ld4(arr + i);
    float4 xm = w1 ? ld4(arr + i - Zq) : Zv;
    float4 xp = e1 ? ld4(arr + i + Zq) : Zv;
    float4 ym = n1 ? ld4(arr + i - WZ) : Zv;
    float4 yp = s1 ? ld4(arr + i + WZ) : Zv;
    *cen = c;
    return lap(c, xm, xp, ym, yp, z0);
}

__device__ __forceinline__ void block_reduce_add(float val, double* target) {
    __syncthreads();
    #pragma unroll
    for (int o = 16; o; o >>= 1)
        val += __shfl_xor_sync(0xffffffffu, val, o);
    __shared__ double sh[NT / 32];
    int lane = threadIdx.x & 31, wid = threadIdx.x >> 5;
    if (lane == 0) sh[wid] = (double)val;
    __syncthreads();
    if (threadIdx.x == 0) {
        double s = 0.0;
        #pragma unroll
        for (int k = 0; k < NT / 32; ++k) s += sh[k];
        atomicAdd(target, s);
    }
}

__device__ __forceinline__ void block_reduce4(float v0, float v1, float v2,
                                              float v3, double* t0, double* t1,
                                              double* t2, double* t3) {
    __syncthreads();
    #pragma unroll
    for (int o = 16; o; o >>= 1) {
        v0 += __shfl_xor_sync(0xffffffffu, v0, o);
        v1 += __shfl_xor_sync(0xffffffffu, v1, o);
        v2 += __shfl_xor_sync(0xffffffffu, v2, o);
        v3 += __shfl_xor_sync(0xffffffffu, v3, o);
    }
    __shared__ double sh[4][NT / 32];
    int lane = threadIdx.x & 31, wid = threadIdx.x >> 5;
    if (lane == 0) {
        sh[0][wid] = v0; sh[1][wid] = v1; sh[2][wid] = v2; sh[3][wid] = v3;
    }
    __syncthreads();
    if (threadIdx.x < 4) {
        double s = 0.0;
        #pragma unroll
        for (int k = 0; k < NT / 32; ++k) s += sh[threadIdx.x][k];
        double* tgt = (threadIdx.x == 0) ? t0 : (threadIdx.x == 1) ? t1
                    : (threadIdx.x == 2) ? t2 : t3;
        atomicAdd(tgt, s);
    }
}

__device__ __forceinline__ void block_reduce_max(float val, unsigned* target) {
    __syncthreads();
    #pragma unroll
    for (int o = 16; o; o >>= 1)
        val = fmaxf(val, __shfl_xor_sync(0xffffffffu, val, o));
    __shared__ float shm[NT / 32];
    int lane = threadIdx.x & 31, wid = threadIdx.x >> 5;
    if (lane == 0) shm[wid] = val;
    __syncthreads();
    if (threadIdx.x == 0) {
        float m = 0.f;
        #pragma unroll
        for (int k = 0; k < NT / 32; ++k) m = fmaxf(m, shm[k]);
        atomicMax(target, __float_as_uint(m));
    }
}

// per-sample grid barrier: only the SBLK blocks of sample sb participate.
__device__ __forceinline__ void sample_sync(int sb) {
    __syncthreads();
    if (threadIdx.x == 0) {
        unsigned my = *(volatile unsigned*)&g_bar_gen[sb];   // read BEFORE arrive
        __threadfence();
        if (atomicAdd(&g_bar_count[sb], 1) == SBLK - 1) {
            g_bar_count[sb] = 0;
            __threadfence();
            atomicAdd(&g_bar_gen[sb], 1);
        } else {
            while (*(volatile unsigned*)&g_bar_gen[sb] == my) __nanosleep(64);
        }
        __threadfence();
    }
    __syncthreads();
}

__device__ __forceinline__ void decode(int sb, int t, int& i, int& z0,
                                       int& wi, int& h) {
    i  = (sb << 22) + (t * NT + (int)threadIdx.x) * 4;
    z0 = i & 63;
    wi = (i >> 6) & 255;
    h  = (i >> 14) & 255;
}

// Scalar replay (double, fixed op order — deterministic on every block):
// alpha_{k-1} and beta_k from the stored dot arrays.
//   eta_0 = tau_0; alpha_j = rho_j/(eta_j+EPS)
//   beta_{j+1} = (rho_j - 2 a tau_j + a^2 om_j)/(rho_j+EPS)
//   eta_{j+1} = tau_{j+1} + b sig_{j+1} + b^2 eta_j
__device__ __forceinline__ void replay(int k, int sb, double& al, double& bt) {
    double eta = __ldcg(&g_tau[0][sb]);
    al = 0.0; bt = 0.0;
    for (int j = 1; j <= k; ++j) {
        double r = __ldcg(&g_rho[j - 1][sb]);
        double t = __ldcg(&g_tau[j - 1][sb]);
        double o = __ldcg(&g_om [j - 1][sb]);
        al = r / (eta + EPS);
        double rr = r - 2.0 * al * t + al * al * o;
        bt = rr / (r + EPS);
        if (j < k) {
            double tj = __ldcg(&g_tau[j][sb]);
            double sj = __ldcg(&g_sig[j][sb]);
            eta = tj + bt * sj + bt * bt * eta;
        }
    }
}

// ---------------------------------------------------------------------------
// kernels
// ---------------------------------------------------------------------------

__global__ void k_zero() {
    int t = threadIdx.x;
    if (t < ITER * Bq) {
        ((double*)g_rho)[t] = 0.0;
        ((double*)g_tau)[t] = 0.0;
        ((double*)g_sig)[t] = 0.0;
        ((double*)g_om)[t]  = 0.0;
    }
    if (t == 0) { g_loss = 0.0; g_max = 0u; }
}

__global__ void __launch_bounds__(NT, OCC)
k_cg(const float* __restrict__ x0, const float* __restrict__ bin,
     const float* __restrict__ ref, float* __restrict__ out) {
    const int sb   = (int)blockIdx.x & 3;
    const int sblk = (int)blockIdx.x >> 2;   // 0..SBLK-1
    __shared__ float s_a, s_b;

    // ---- P0 (asc): r0 = b - A x0 ; rho0 ----
    {
        float acc = 0.f;
        for (int t = sblk; t < TPS; t += SBLK) {
            int i, z0, wi, h; decode(sb, t, i, z0, wi, h);
            float4 xc;
            float4 ax = lap_of(x0, i, z0, wi > 0, wi < Wq - 1,
                               h > 0, h < Hq - 1, &xc);
            float4 bb = ld4cs(bin + i);
            float4 r0 = make_float4(bb.x - ax.x, bb.y - ax.y,
                                    bb.z - ax.z, bb.w - ax.w);
            st4(g_r[0] + i, r0);
            acc += dot4(r0, r0);
        }
        block_reduce_add(acc, &g_rho[0][sb]);
    }
    sample_sync(sb);

    // ---- P1 (desc): w0 = A r0 (store) ; tau0 = r0.w0 ; om0 = w0.w0 ----
    {
        float accT = 0.f, accO = 0.f;
        for (int t = sblk; t < TPS; t += SBLK) {
            int tt = TPS - 1 - t;
            int i, z0, wi, h; decode(sb, tt, i, z0, wi, h);
            float4 rc;
            float4 w = lap_of(g_r[0], i, z0, wi > 0, wi < Wq - 1,
                              h > 0, h < Hq - 1, &rc);
            st4(g_w[0] + i, w);
            accT += dot4(rc, w);
            accO += dot4(w, w);
        }
        block_reduce4(accT, accO, 0.f, 0.f,
                      &g_tau[0][sb], &g_om[0][sb],
                      &g_sig[0][sb], &g_sig[0][sb]);
    }
    sample_sync(sb);

    // ---- phases k = 1..7: two 7-pt stencils (r,w), one CG iter each.
    //      k=7: pure-read phase (neither r_7 nor w_7 stored) ----
    for (int k = 1; k < ITER; ++k) {
        if (threadIdx.x == 0) {
            double al, bt;
            replay(k, sb, al, bt);      // alpha_{k-1}, beta_k
            s_a = (float)al;
            s_b = (float)bt;
        }
        __syncthreads();
        const float al = s_a, bk = s_b;
        const float* rin = g_r[k - 1];
        const float* win = g_w[k - 1];
        const bool last = (k == ITER - 1);
        float* rout = last ? nullptr : g_r[k];
        float* wout = last ? nullptr : g_w[k];
        const bool rev = !(k & 1);
        float accR = 0.f, accT = 0.f, accS = 0.f, accO = 0.f;

        for (int t = sblk; t < TPS; t += SBLK) {
            int tt = rev ? TPS - 1 - t : t;
            int i, z0, wi, h; decode(sb, tt, i, z0, wi, h);
            bool w1 = wi > 0, e1 = wi < Wq - 1, n1 = h > 0, s1 = h < Hq - 1;

            float4 rc, wc;
            float4 lr = lap_of(rin, i, z0, w1, e1, n1, s1, &rc);  // A r_{k-1}
            float4 lw = lap_of(win, i, z0, w1, e1, n1, s1, &wc);  // A w_{k-1}

            // r_k = r_{k-1} - alpha w_{k-1}
            float4 rk = make_float4(rc.x - al * wc.x, rc.y - al * wc.y,
                                    rc.z - al * wc.z, rc.w - al * wc.w);
            if (!last) st4(rout + i, rk);
            // A r_k = A r_{k-1} - alpha A w_{k-1}
            float4 ark = make_float4(lr.x - al * lw.x, lr.y - al * lw.y,
                                     lr.z - al * lw.z, lr.w - al * lw.w);
            // w_k = A r_k + beta_k w_{k-1}
            float4 wk = make_float4(ark.x + bk * wc.x, ark.y + bk * wc.y,
                                    ark.z + bk * wc.z, ark.w + bk * wc.w);
            if (!last) st4(wout + i, wk);

            accR += dot4(rk, rk);
            accT += dot4(rk, wk);
            accS += dot4(rk, wc);
            accO += dot4(wk, wk);
        }
        block_reduce4(accR, accT, accS, accO,
                      &g_rho[k][sb], &g_tau[k][sb],
                      &g_sig[k][sb], &g_om[k][sb]);
        sample_sync(sb);
    }

    // ---- final (desc): x = x0 + sum_{j<=6} c'_j r_j + d*w6 ----
    // c_7 = alpha_7 ; c_j = alpha_j + beta_{j+1} c_{j+1}
    // r_7 = r_6 - alpha_6 w_6  =>  c'_6 = c_6 + c_7 ; d = -c_7*alpha_6
    {
        __shared__ float s_c[ITER];   // s_c[0..6] for r_0..r_6, s_c[7] for w6
        if (threadIdx.x == 0) {
            double alpha[ITER], beta[ITER];
            double eta = __ldcg(&g_tau[0][sb]);
            for (int j = 0; j < ITER; ++j) {
                double r = __ldcg(&g_rho[j][sb]);
                double a = r / (eta + EPS);
                alpha[j] = a;
                if (j < ITER - 1) {
                    double t = __ldcg(&g_tau[j][sb]);
                    double o = __ldcg(&g_om[j][sb]);
                    double rr = r - 2.0 * a * t + a * a * o;
                    double b = rr / (r + EPS);
                    beta[j + 1] = b;
                    double tj = __ldcg(&g_tau[j + 1][sb]);
                    double sj = __ldcg(&g_sig[j + 1][sb]);
                    eta = tj + b * sj + b * b * eta;
                }
            }
            double c[ITER];
            c[ITER - 1] = alpha[ITER - 1];
            for (int j = ITER - 2; j >= 0; --j)
                c[j] = alpha[j] + beta[j + 1] * c[j + 1];
            for (int j = 0; j < ITER - 2; ++j) s_c[j] = (float)c[j];
            s_c[ITER - 2] = (float)(c[ITER - 2] + c[ITER - 1]);       // r_6
            s_c[ITER - 1] = (float)(-c[ITER - 1] * alpha[ITER - 2]);  // w_6
        }
        __syncthreads();

        float accL = 0.f, mx = 0.f;
        for (int t = sblk; t < TPS; t += SBLK) {
            int tt = TPS - 1 - t;
            int i, z0, wi, h; decode(sb, tt, i, z0, wi, h);
            float4 x = ld4cs(x0 + i);
            #pragma unroll
            for (int k = 0; k < ITER - 1; ++k) {
                float c = s_c[k];
                float4 rk = ld4cs(g_r[k] + i);
                x.x += c * rk.x; x.y += c * rk.y;
                x.z += c * rk.z; x.w += c * rk.w;
            }
            {
                float d = s_c[ITER - 1];
                float4 w6 = ld4cs(g_w[ITER - 2] + i);
                x.x += d * w6.x; x.y += d * w6.y;
                x.z += d * w6.z; x.w += d * w6.w;
            }
            __stcs(out + 1 + i + 0, x.x);
            __stcs(out + 1 + i + 1, x.y);
            __stcs(out + 1 + i + 2, x.z);
            __stcs(out + 1 + i + 3, x.w);

            float4 rf = ld4cs(ref + i);
            float dx = x.x - rf.x, dy = x.y - rf.y;
            float dz = x.z - rf.z, dw = x.w - rf.w;
            accL += dx * dx + dy * dy + dz * dz + dw * dw;
            mx = fmaxf(mx, fmaxf(fmaxf(fabsf(dx), fabsf(dy)),
                                 fmaxf(fabsf(dz), fabsf(dw))));
        }
        block_reduce_add(accL, &g_loss);
        block_reduce_max(mx, &g_max);
    }
}

__global__ void k_writeout(float* __restrict__ out) {
    out[0] = (float)(g_loss / (double)N);
    out[N + 1] = __uint_as_float(g_max);
    // rho_8 per sample via the same scalar replay + one recurrence step
    double s = 0.0;
    for (int sb = 0; sb < Bq; ++sb) {
        double eta = g_tau[0][sb];
        double rho8 = 0.0;
        for (int j = 0; j < ITER; ++j) {
            double r = g_rho[j][sb];
            double a = r / (eta + EPS);
            double t = g_tau[j][sb];
            double o = g_om[j][sb];
            double rr = r - 2.0 * a * t + a * a * o;
            if (j == ITER - 1) { rho8 = rr; break; }
            double b = rr / (r + EPS);
            double tj = g_tau[j + 1][sb];
            double sj = g_sig[j + 1][sb];
            eta = tj + b * sj + b * b * eta;
        }
        s += rho8;
    }
    out[N + 2] = (float)(s / (double)Bq);
}

// ---------------------------------------------------------------------------

extern "C" void kernel_launch(void* const* d_in, const int* in_sizes, int n_in,
                              void* d_out, int out_size) {
    const float* x   = (const float*)d_in[0];
    const float* b   = (const float*)d_in[1];
    const float* ref = (const float*)d_in[2];
    float* out = (float*)d_out;

    k_zero<<<1, 64>>>();
    k_cg<<<GRID, NT>>>(x, b, ref, out);
    k_writeout<<<1, 1>>>(out);
}